// round 7
// baseline (speedup 1.0000x reference)
#include <cuda_runtime.h>
#include <cuda_bf16.h>
#include <math.h>
#include <stdint.h>

#define NB     4096
#define NROWS  8192
#define DDIM   128
#define NTILE  64          // 8192 / 128
#define NCTA   2080        // NTILE*(NTILE+1)/2 upper-triangle tiles
#define GRIDP  152         // persistent CTAs (1 per SM)
#define E2LOG2 2.885390081777927f   // 2 * log2(e)

// ---------------- static scratch (no allocations allowed) ----------------
__device__ __nv_bfloat16 g_hi[NROWS * DDIM];
__device__ float         g_rowsum[NROWS];
__device__ float         g_pos[NROWS];
__device__ float         g_self[NROWS];

// ---------------- helpers ----------------
__device__ __forceinline__ uint32_t smem_u32(const void* p) {
    uint32_t a;
    asm("{ .reg .u64 t; cvta.to.shared.u64 t, %1; cvt.u32.u64 %0, t; }"
        : "=r"(a) : "l"(p));
    return a;
}
__device__ __forceinline__ void ldsm4(uint32_t* r, uint32_t addr) {
    asm volatile("ldmatrix.sync.aligned.m8n8.x4.shared.b16 {%0,%1,%2,%3}, [%4];"
                 : "=r"(r[0]), "=r"(r[1]), "=r"(r[2]), "=r"(r[3]) : "r"(addr));
}
__device__ __forceinline__ void mma16816(float* d, const uint32_t* a,
                                         uint32_t b0, uint32_t b1) {
    asm volatile("mma.sync.aligned.m16n8k16.row.col.f32.bf16.bf16.f32 "
                 "{%0,%1,%2,%3}, {%4,%5,%6,%7}, {%8,%9}, {%0,%1,%2,%3};"
                 : "+f"(d[0]), "+f"(d[1]), "+f"(d[2]), "+f"(d[3])
                 : "r"(a[0]), "r"(a[1]), "r"(a[2]), "r"(a[3]), "r"(b0), "r"(b1));
}
__device__ __forceinline__ void cp16(uint32_t dst, const void* src) {
    asm volatile("cp.async.cg.shared.global [%0], [%1], 16;"
                 :: "r"(dst), "l"(src) : "memory");
}
#define CP_COMMIT() asm volatile("cp.async.commit_group;" ::: "memory")
#define CP_WAIT0()  asm volatile("cp.async.wait_group 0;" ::: "memory")

// smem: two tile buffers (A 128 rows + B 128 rows each, pitch 272) + reductions
#define PITCH    272
#define BUFSZ    (256 * PITCH)       // 69632 per buffer
#define SM_ROWS  (2 * BUFSZ)
#define SM_COLS  (SM_ROWS + 128 * 4)
#define SMEM_SZ  (SM_COLS + 128 * 4)

__device__ __forceinline__ void decode_tile(int t, int& bi, int& bj) {
    int x = (int)(64.5f - sqrtf(64.5f * 64.5f - 2.0f * (float)t));
    while (x * NTILE - (x * (x - 1)) / 2 > t) --x;
    while ((x + 1) * NTILE - ((x + 1) * x) / 2 <= t) ++x;
    bi = x;
    bj = x + (t - (x * NTILE - (x * (x - 1)) / 2));
}

// ---------------- K1: normalize, bf16, positives/self (2 pairs per warp) ----------------
__global__ void __launch_bounds__(256) k_norm(const float* __restrict__ p1,
                                              const float* __restrict__ p2) {
    int w    = (blockIdx.x * blockDim.x + threadIdx.x) >> 5;
    int lane = threadIdx.x & 31;
    int g0 = 2 * w;
    if (g0 >= NB) return;
    float4 va1 = *(const float4*)(p1 + (size_t)g0 * DDIM + lane * 4);
    float4 va2 = *(const float4*)(p2 + (size_t)g0 * DDIM + lane * 4);
    float4 vb1 = *(const float4*)(p1 + (size_t)(g0 + 1) * DDIM + lane * 4);
    float4 vb2 = *(const float4*)(p2 + (size_t)(g0 + 1) * DDIM + lane * 4);

    float sa1 = va1.x*va1.x + va1.y*va1.y + va1.z*va1.z + va1.w*va1.w;
    float sa2 = va2.x*va2.x + va2.y*va2.y + va2.z*va2.z + va2.w*va2.w;
    float cxa = va1.x*va2.x + va1.y*va2.y + va1.z*va2.z + va1.w*va2.w;
    float sb1 = vb1.x*vb1.x + vb1.y*vb1.y + vb1.z*vb1.z + vb1.w*vb1.w;
    float sb2 = vb2.x*vb2.x + vb2.y*vb2.y + vb2.z*vb2.z + vb2.w*vb2.w;
    float cxb = vb1.x*vb2.x + vb1.y*vb2.y + vb1.z*vb2.z + vb1.w*vb2.w;
#pragma unroll
    for (int o = 16; o; o >>= 1) {
        sa1 += __shfl_xor_sync(0xffffffffu, sa1, o);
        sa2 += __shfl_xor_sync(0xffffffffu, sa2, o);
        cxa += __shfl_xor_sync(0xffffffffu, cxa, o);
        sb1 += __shfl_xor_sync(0xffffffffu, sb1, o);
        sb2 += __shfl_xor_sync(0xffffffffu, sb2, o);
        cxb += __shfl_xor_sync(0xffffffffu, cxb, o);
    }
    float ia1 = 1.0f / fmaxf(sqrtf(sa1), 1e-12f);
    float ia2 = 1.0f / fmaxf(sqrtf(sa2), 1e-12f);
    float ib1 = 1.0f / fmaxf(sqrtf(sb1), 1e-12f);
    float ib2 = 1.0f / fmaxf(sqrtf(sb2), 1e-12f);

    float4  vs[4]  = {va1, vb1, va2, vb2};
    float   is[4]  = {ia1, ib1, ia2, ib2};
    int     rw[4]  = {g0, g0 + 1, g0 + NB, g0 + 1 + NB};
#pragma unroll
    for (int q = 0; q < 4; ++q) {
        float4 v = vs[q]; float inv = is[q];
        v.x *= inv; v.y *= inv; v.z *= inv; v.w *= inv;
        size_t base = (size_t)rw[q] * DDIM + lane * 4;
        __nv_bfloat162 h01; h01.x = __float2bfloat16(v.x); h01.y = __float2bfloat16(v.y);
        __nv_bfloat162 h23; h23.x = __float2bfloat16(v.z); h23.y = __float2bfloat16(v.w);
        *(__nv_bfloat162*)(g_hi + base)     = h01;
        *(__nv_bfloat162*)(g_hi + base + 2) = h23;
    }
    if (lane == 0) {
        float pa = cxa * ia1 * ia2, pb = cxb * ib1 * ib2;
        g_pos[g0] = pa;           g_pos[g0 + NB] = pa;
        g_pos[g0 + 1] = pb;       g_pos[g0 + 1 + NB] = pb;
        g_self[g0]     = sa1 * ia1 * ia1;  g_self[g0 + NB]     = sa2 * ia2 * ia2;
        g_self[g0 + 1] = sb1 * ib1 * ib1;  g_self[g0 + 1 + NB] = sb2 * ib2 * ib2;
        g_rowsum[g0] = 0.0f;      g_rowsum[g0 + NB] = 0.0f;
        g_rowsum[g0 + 1] = 0.0f;  g_rowsum[g0 + 1 + NB] = 0.0f;
    }
}

// ---------------- K2: persistent double-buffered HMMA sim-GEMM ----------------
extern __shared__ char smem_raw[];

__device__ __forceinline__ void prefetch_tile(int bi, int bj, uint32_t sbuf, int tid) {
#pragma unroll
    for (int i = 0; i < 8; ++i) {
        int idx = tid + i * 512;
        int row = idx >> 4;
        int seg = idx & 15;
        int grow = (row < 128) ? bi * 128 + row : bj * 128 + (row - 128);
        cp16(sbuf + (uint32_t)(row * PITCH + seg * 16),
             g_hi + (size_t)grow * DDIM + seg * 8);
    }
    CP_COMMIT();
}

__global__ void __launch_bounds__(512, 1) k_gemm() {
    const int tid  = threadIdx.x;
    const int wid  = tid >> 5;
    const int lane = tid & 31;
    const int wm = wid >> 2;    // 0..3 -> rows 32*wm
    const int wn = wid & 3;     // 0..3 -> cols 32*wn

    const uint32_t sb = smem_u32(smem_raw);
    float* smrows = (float*)(smem_raw + SM_ROWS);
    float* smcols = (float*)(smem_raw + SM_COLS);
    if (tid < 128) { smrows[tid] = 0.0f; smcols[tid] = 0.0f; }

    int t = blockIdx.x;
    if (t < NCTA) {
        int bi0, bj0;
        decode_tile(t, bi0, bj0);
        prefetch_tile(bi0, bj0, sb, tid);
    }
    int cur = 0;

    while (t < NCTA) {
        int bi, bj;
        decode_tile(t, bi, bj);
        const bool diag = (bi == bj);
        const int r0 = bi * 128;
        const int c0 = bj * 128;

        CP_WAIT0();
        __syncthreads();                       // S1: buf[cur] ready, reductions zeroed

        int tn = t + GRIDP;
        if (tn < NCTA) {
            int nbi, nbj;
            decode_tile(tn, nbi, nbj);
            prefetch_tile(nbi, nbj, sb + (cur ^ 1) * BUFSZ, tid);
        }

        const uint32_t bo = sb + cur * BUFSZ;
        const uint32_t a_base = bo +
            (uint32_t)((32 * wm + (lane & 15)) * PITCH + (lane >> 4) * 16);
        const int brow = 32 * wn + (lane & 7) + ((lane >> 4) << 3);
        const uint32_t b_base = bo + 128 * PITCH +
            (uint32_t)(brow * PITCH + ((lane >> 3) & 1) * 16);

        float acc[2][4][4];
#pragma unroll
        for (int mi = 0; mi < 2; ++mi)
#pragma unroll
            for (int nj = 0; nj < 4; ++nj)
#pragma unroll
                for (int e = 0; e < 4; ++e) acc[mi][nj][e] = 0.0f;

#pragma unroll
        for (int kk = 0; kk < 8; ++kk) {
            uint32_t b0[4], b1[4];
            ldsm4(b0, b_base + kk * 32);
            ldsm4(b1, b_base + 16 * PITCH + kk * 32);
#pragma unroll
            for (int mi = 0; mi < 2; ++mi) {
                uint32_t a[4];
                ldsm4(a, a_base + kk * 32 + mi * 16 * PITCH);
                mma16816(acc[mi][0], a, b0[0], b0[1]);
                mma16816(acc[mi][1], a, b0[2], b0[3]);
                mma16816(acc[mi][2], a, b1[0], b1[1]);
                mma16816(acc[mi][3], a, b1[2], b1[3]);
            }
        }

        // exp(2*sim) = exp2(E2LOG2 * sim)
#pragma unroll
        for (int mi = 0; mi < 2; ++mi)
#pragma unroll
            for (int nj = 0; nj < 4; ++nj)
#pragma unroll
                for (int e = 0; e < 4; ++e)
                    acc[mi][nj][e] = exp2f(E2LOG2 * acc[mi][nj][e]);

        // row partial sums
        const int rbase = 32 * wm + (lane >> 2);
#pragma unroll
        for (int mi = 0; mi < 2; ++mi) {
            float slo = 0.0f, shi = 0.0f;
#pragma unroll
            for (int nj = 0; nj < 4; ++nj) {
                slo += acc[mi][nj][0] + acc[mi][nj][1];
                shi += acc[mi][nj][2] + acc[mi][nj][3];
            }
            slo += __shfl_xor_sync(0xffffffffu, slo, 1);
            slo += __shfl_xor_sync(0xffffffffu, slo, 2);
            shi += __shfl_xor_sync(0xffffffffu, shi, 1);
            shi += __shfl_xor_sync(0xffffffffu, shi, 2);
            if ((lane & 3) == 0) {
                atomicAdd(&smrows[rbase + 16 * mi],     slo);
                atomicAdd(&smrows[rbase + 16 * mi + 8], shi);
            }
        }

        // column partial sums (off-diagonal tiles credit the transpose rows)
        if (!diag) {
#pragma unroll
            for (int nj = 0; nj < 4; ++nj) {
#pragma unroll
                for (int c2 = 0; c2 < 2; ++c2) {
                    float v = acc[0][nj][c2] + acc[0][nj][c2 + 2]
                            + acc[1][nj][c2] + acc[1][nj][c2 + 2];
                    v += __shfl_down_sync(0xffffffffu, v, 16);
                    v += __shfl_down_sync(0xffffffffu, v, 8);
                    v += __shfl_down_sync(0xffffffffu, v, 4);
                    if (lane < 4)
                        atomicAdd(&smcols[32 * wn + 8 * nj + lane * 2 + c2], v);
                }
            }
        }
        __syncthreads();                       // S2: all smem atomics done
        if (tid < 128) {
            atomicAdd(&g_rowsum[r0 + tid], smrows[tid]);
            if (!diag) atomicAdd(&g_rowsum[c0 + tid], smcols[tid]);
            smrows[tid] = 0.0f; smcols[tid] = 0.0f;
        }
        cur ^= 1;
        t = tn;
    }
}

// ---------------- K3: final reduction ----------------
__global__ void __launch_bounds__(1024) k_final(float* __restrict__ out) {
    __shared__ float red[1024];
    int tid = threadIdx.x;
    float local = 0.0f;
#pragma unroll
    for (int r = tid; r < NROWS; r += 1024) {
        float den = g_rowsum[r] - exp2f(E2LOG2 * g_self[r]);
        local += __logf(den) - 2.0f * g_pos[r];
    }
    red[tid] = local;
    __syncthreads();
#pragma unroll
    for (int o = 512; o; o >>= 1) {
        if (tid < o) red[tid] += red[tid + o];
        __syncthreads();
    }
    if (tid == 0) out[0] = red[0] / (float)NROWS;
}

// ---------------- launcher ----------------
extern "C" void kernel_launch(void* const* d_in, const int* in_sizes, int n_in,
                              void* d_out, int out_size) {
    const float* p1 = (const float*)d_in[0];
    const float* p2 = (const float*)d_in[1];
    float* out = (float*)d_out;

    cudaFuncSetAttribute(k_gemm, cudaFuncAttributeMaxDynamicSharedMemorySize, SMEM_SZ);

    k_norm<<<NB / 16, 256>>>(p1, p2);
    k_gemm<<<GRIDP, 512, SMEM_SZ>>>();
    k_final<<<1, 1024>>>(out);
}

// round 8
// speedup vs baseline: 1.4777x; 1.4777x over previous
#include <cuda_runtime.h>
#include <cuda_fp16.h>
#include <math.h>
#include <stdint.h>

#define NB     4096
#define NROWS  8192
#define DDIM   128
#define NTILE  64          // 8192 / 128
#define NCTA   2080        // NTILE*(NTILE+1)/2 upper-triangle tiles
#define E2LOG2 2.885390081777927f   // 2 * log2(e)

// ---------------- static scratch (no allocations allowed) ----------------
__device__ __half g_hi[NROWS * DDIM];
__device__ float  g_rowsum[NROWS];
__device__ float  g_pos[NROWS];
__device__ float  g_self[NROWS];

// ---------------- helpers ----------------
__device__ __forceinline__ uint32_t smem_u32(const void* p) {
    uint32_t a;
    asm("{ .reg .u64 t; cvta.to.shared.u64 t, %1; cvt.u32.u64 %0, t; }"
        : "=r"(a) : "l"(p));
    return a;
}
__device__ __forceinline__ void ldsm4(uint32_t* r, uint32_t addr) {
    asm volatile("ldmatrix.sync.aligned.m8n8.x4.shared.b16 {%0,%1,%2,%3}, [%4];"
                 : "=r"(r[0]), "=r"(r[1]), "=r"(r[2]), "=r"(r[3]) : "r"(addr));
}
// f16 accumulate MMA: D(f16x2 x2) = A*B + D
__device__ __forceinline__ void mma_h(uint32_t* d, const uint32_t* a,
                                      uint32_t b0, uint32_t b1) {
    asm volatile("mma.sync.aligned.m16n8k16.row.col.f16.f16.f16.f16 "
                 "{%0,%1}, {%2,%3,%4,%5}, {%6,%7}, {%0,%1};"
                 : "+r"(d[0]), "+r"(d[1])
                 : "r"(a[0]), "r"(a[1]), "r"(a[2]), "r"(a[3]), "r"(b0), "r"(b1));
}
__device__ __forceinline__ uint32_t hmul2(uint32_t a, uint32_t b) {
    uint32_t o; asm("mul.rn.f16x2 %0, %1, %2;" : "=r"(o) : "r"(a), "r"(b)); return o;
}
__device__ __forceinline__ uint32_t hadd2(uint32_t a, uint32_t b) {
    uint32_t o; asm("add.rn.f16x2 %0, %1, %2;" : "=r"(o) : "r"(a), "r"(b)); return o;
}
__device__ __forceinline__ uint32_t hex2(uint32_t a) {
    uint32_t o; asm("ex2.approx.f16x2 %0, %1;" : "=r"(o) : "r"(a)); return o;
}
__device__ __forceinline__ float2 h2f2(uint32_t h) {
    __half2 v = *reinterpret_cast<__half2*>(&h);
    return __half22float2(v);
}
__device__ __forceinline__ void cp16(uint32_t dst, const void* src) {
    asm volatile("cp.async.cg.shared.global [%0], [%1], 16;"
                 :: "r"(dst), "l"(src) : "memory");
}
#define CP_COMMIT() asm volatile("cp.async.commit_group;" ::: "memory")
#define CP_WAIT0()  asm volatile("cp.async.wait_group 0;" ::: "memory")

// smem tile layout: 128 rows, pitch 272 B (17x16B -> conflict-free ldmatrix)
#define PITCH    272
#define SM_A     0
#define SM_B     (128 * PITCH)
#define SM_ROWS  (2 * 128 * PITCH)
#define SM_COLS  (SM_ROWS + 128 * 4)
#define SMEM_SZ  (SM_COLS + 128 * 4)

// ---------------- K1: normalize pair + f16 + positives/self ----------------
__global__ void __launch_bounds__(256) k_norm(const float* __restrict__ p1,
                                              const float* __restrict__ p2) {
    int gw = (blockIdx.x * blockDim.x + threadIdx.x) >> 5;   // pair index 0..NB-1
    int lane = threadIdx.x & 31;
    if (gw >= NB) return;
    float4 v1 = *(const float4*)(p1 + (size_t)gw * DDIM + lane * 4);
    float4 v2 = *(const float4*)(p2 + (size_t)gw * DDIM + lane * 4);
    float ss1 = v1.x * v1.x + v1.y * v1.y + v1.z * v1.z + v1.w * v1.w;
    float ss2 = v2.x * v2.x + v2.y * v2.y + v2.z * v2.z + v2.w * v2.w;
    float cx  = v1.x * v2.x + v1.y * v2.y + v1.z * v2.z + v1.w * v2.w;
#pragma unroll
    for (int o = 16; o; o >>= 1) {
        ss1 += __shfl_xor_sync(0xffffffffu, ss1, o);
        ss2 += __shfl_xor_sync(0xffffffffu, ss2, o);
        cx  += __shfl_xor_sync(0xffffffffu, cx,  o);
    }
    float inv1 = 1.0f / fmaxf(sqrtf(ss1), 1e-12f);
    float inv2 = 1.0f / fmaxf(sqrtf(ss2), 1e-12f);

#pragma unroll
    for (int half = 0; half < 2; ++half) {
        float4 v = half ? v2 : v1;
        float inv = half ? inv2 : inv1;
        size_t base = (size_t)(half ? gw + NB : gw) * DDIM + lane * 4;
        v.x *= inv; v.y *= inv; v.z *= inv; v.w *= inv;
        *(__half2*)(g_hi + base)     = __floats2half2_rn(v.x, v.y);
        *(__half2*)(g_hi + base + 2) = __floats2half2_rn(v.z, v.w);
    }
    if (lane == 0) {
        float pos = cx * inv1 * inv2;
        g_pos[gw] = pos;            g_pos[gw + NB] = pos;
        g_self[gw] = ss1 * inv1 * inv1;
        g_self[gw + NB] = ss2 * inv2 * inv2;
        g_rowsum[gw] = 0.0f;        g_rowsum[gw + NB] = 0.0f;
    }
}

// ---------------- K2: HMMA(f16 acc) sim-GEMM (upper triangle) ----------------
extern __shared__ char smem_raw[];

__global__ void __launch_bounds__(256, 3) k_gemm() {
    const int tid  = threadIdx.x;
    const int wid  = tid >> 5;
    const int lane = tid & 31;

    // decode upper-triangle tile (bi <= bj) from linear blockIdx
    int t = blockIdx.x;
    int bi = (int)(64.5f - sqrtf(64.5f * 64.5f - 2.0f * (float)t));
    while (bi * NTILE - (bi * (bi - 1)) / 2 > t) --bi;
    while ((bi + 1) * NTILE - ((bi + 1) * bi) / 2 <= t) ++bi;
    const int bj = bi + (t - (bi * NTILE - (bi * (bi - 1)) / 2));
    const bool diag = (bi == bj);
    const int r0 = bi * 128;
    const int c0 = bj * 128;

    const uint32_t sb = smem_u32(smem_raw);
    float* smrows = (float*)(smem_raw + SM_ROWS);
    float* smcols = (float*)(smem_raw + SM_COLS);
    if (tid < 128) { smrows[tid] = 0.0f; smcols[tid] = 0.0f; }

    // async load A (rows r0..+127) and B (rows c0..+127)
#pragma unroll
    for (int it = 0; it < 8; ++it) {
        int idx = tid + it * 256;
        int row = idx >> 4;
        int seg = idx & 15;
        uint32_t so = (uint32_t)(row * PITCH + seg * 16);
        cp16(sb + SM_A + so, g_hi + (size_t)(r0 + row) * DDIM + seg * 8);
        cp16(sb + SM_B + so, g_hi + (size_t)(c0 + row) * DDIM + seg * 8);
    }
    CP_COMMIT();
    CP_WAIT0();
    __syncthreads();

    const int wm = wid >> 2;          // 0..1 -> rows 64*wm
    const int wn = wid & 3;           // 0..3 -> cols 32*wn

    const uint32_t a_base = sb +
        (uint32_t)((64 * wm + (lane & 15)) * PITCH + (lane >> 4) * 16);
    const int brow = 32 * wn + (lane & 7) + ((lane >> 4) << 3);
    const uint32_t b_base = sb + SM_B +
        (uint32_t)(brow * PITCH + ((lane >> 3) & 1) * 16);

    uint32_t acc[4][4][2];            // f16x2 accumulators
#pragma unroll
    for (int mi = 0; mi < 4; ++mi)
#pragma unroll
        for (int nj = 0; nj < 4; ++nj) { acc[mi][nj][0] = 0u; acc[mi][nj][1] = 0u; }

#pragma unroll
    for (int kk = 0; kk < 8; ++kk) {
        uint32_t b0[4], b1[4];
        ldsm4(b0, b_base + kk * 32);
        ldsm4(b1, b_base + 16 * PITCH + kk * 32);
#pragma unroll
        for (int mi = 0; mi < 4; ++mi) {
            uint32_t a[4];
            ldsm4(a, a_base + kk * 32 + mi * 16 * PITCH);
            mma_h(acc[mi][0], a, b0[0], b0[1]);
            mma_h(acc[mi][1], a, b0[2], b0[3]);
            mma_h(acc[mi][2], a, b1[0], b1[1]);
            mma_h(acc[mi][3], a, b1[2], b1[3]);
        }
    }

    // exp(2*sim) = exp2(E2LOG2 * sim) in f16x2 (2 exps per MUFU op)
    const __half2 sc2h = __float2half2_rn(E2LOG2);
    const uint32_t sc2 = *reinterpret_cast<const uint32_t*>(&sc2h);
#pragma unroll
    for (int mi = 0; mi < 4; ++mi)
#pragma unroll
        for (int nj = 0; nj < 4; ++nj) {
            acc[mi][nj][0] = hex2(hmul2(acc[mi][nj][0], sc2));
            acc[mi][nj][1] = hex2(hmul2(acc[mi][nj][1], sc2));
        }

    // row partial sums: f16x2 tree over nj, quad shfl-reduce, 1 atomic/row/quad
    const int rbase = 64 * wm + (lane >> 2);
#pragma unroll
    for (int mi = 0; mi < 4; ++mi) {
        uint32_t hlo = hadd2(hadd2(acc[mi][0][0], acc[mi][1][0]),
                             hadd2(acc[mi][2][0], acc[mi][3][0]));
        uint32_t hhi = hadd2(hadd2(acc[mi][0][1], acc[mi][1][1]),
                             hadd2(acc[mi][2][1], acc[mi][3][1]));
        float2 flo = h2f2(hlo), fhi = h2f2(hhi);
        float slo = flo.x + flo.y;
        float shi = fhi.x + fhi.y;
        slo += __shfl_xor_sync(0xffffffffu, slo, 1);
        slo += __shfl_xor_sync(0xffffffffu, slo, 2);
        shi += __shfl_xor_sync(0xffffffffu, shi, 1);
        shi += __shfl_xor_sync(0xffffffffu, shi, 2);
        if ((lane & 3) == 0) {
            atomicAdd(&smrows[rbase + 16 * mi],     slo);
            atomicAdd(&smrows[rbase + 16 * mi + 8], shi);
        }
    }

    // column partial sums (off-diagonal tiles credit the transpose rows)
    if (!diag) {
#pragma unroll
        for (int nj = 0; nj < 4; ++nj) {
            uint32_t v2 = hadd2(hadd2(acc[0][nj][0], acc[0][nj][1]),
                                hadd2(acc[1][nj][0], acc[1][nj][1]));
            v2 = hadd2(v2, hadd2(hadd2(acc[2][nj][0], acc[2][nj][1]),
                                 hadd2(acc[3][nj][0], acc[3][nj][1])));
            float2 f = h2f2(v2);
            float ve = f.x, vo = f.y;
            ve += __shfl_down_sync(0xffffffffu, ve, 16);
            ve += __shfl_down_sync(0xffffffffu, ve, 8);
            ve += __shfl_down_sync(0xffffffffu, ve, 4);
            vo += __shfl_down_sync(0xffffffffu, vo, 16);
            vo += __shfl_down_sync(0xffffffffu, vo, 8);
            vo += __shfl_down_sync(0xffffffffu, vo, 4);
            if (lane < 4) {
                atomicAdd(&smcols[32 * wn + 8 * nj + lane * 2],     ve);
                atomicAdd(&smcols[32 * wn + 8 * nj + lane * 2 + 1], vo);
            }
        }
    }
    __syncthreads();
    if (tid < 128) {
        atomicAdd(&g_rowsum[r0 + tid], smrows[tid]);
        if (!diag) atomicAdd(&g_rowsum[c0 + tid], smcols[tid]);
    }
}

// ---------------- K3: final reduction ----------------
__global__ void __launch_bounds__(1024) k_final(float* __restrict__ out) {
    __shared__ float red[1024];
    int tid = threadIdx.x;
    float local = 0.0f;
#pragma unroll
    for (int r = tid; r < NROWS; r += 1024) {
        float den = g_rowsum[r] - exp2f(E2LOG2 * g_self[r]);
        local += __logf(den) - 2.0f * g_pos[r];
    }
    red[tid] = local;
    __syncthreads();
#pragma unroll
    for (int o = 512; o; o >>= 1) {
        if (tid < o) red[tid] += red[tid + o];
        __syncthreads();
    }
    if (tid == 0) out[0] = red[0] / (float)NROWS;
}

// ---------------- launcher ----------------
extern "C" void kernel_launch(void* const* d_in, const int* in_sizes, int n_in,
                              void* d_out, int out_size) {
    const float* p1 = (const float*)d_in[0];
    const float* p2 = (const float*)d_in[1];
    float* out = (float*)d_out;

    cudaFuncSetAttribute(k_gemm, cudaFuncAttributeMaxDynamicSharedMemorySize, SMEM_SZ);

    k_norm<<<NB / 8, 256>>>(p1, p2);
    k_gemm<<<NCTA, 256, SMEM_SZ>>>();
    k_final<<<1, 1024>>>(out);
}